// round 13
// baseline (speedup 1.0000x reference)
#include <cuda_runtime.h>
#include <cstdint>

// Problem constants
#define R_TOTAL 131072      // N*B*H rows
#define BH      32768       // B*H
#define BHD     8388608     // B*DIM
#define TM 128
#define TN 128
#define KC 16               // K-chunk
#define KSW 20              // padded smem row stride (words)
#define NTH 256
#define STG 3               // pipeline stages

#define ABUF   (128 * KSW)          // words per A (or B) stage = 2560
#define STAGEW (2 * ABUF)           // A+B per stage
#define SMB    (STG * STAGEW * 4)   // 61440 bytes

// Scratch (device globals — no allocation allowed in kernel_launch)
__device__ float g_h1[131072 * 512];   // relu(layer1): cols 0-255 axis, 256-511 arg
__device__ float g_s [131072 * 256];   // axis logits
__device__ float g_hb[32768 * 256];    // mean over N of arg-branch h1
__device__ float g_t [32768 * 256];    // gate pre-activation
__device__ float g_w1c[512 * 512];     // folded layer-1 weights
__device__ float g_b1c[512];

// ---------------------------------------------------------------------------
// Prep: fold concat([axis-arg/2, axis+arg/2]) @ W1^T into direct weights on
// [axis, arg]:  coeff(axis) = Wlo + Whi ; coeff(arg) = (Whi - Wlo)/2
// ---------------------------------------------------------------------------
__global__ void prep_kernel(const float* __restrict__ Wax1, const float* __restrict__ bax1,
                            const float* __restrict__ Warg1, const float* __restrict__ barg1)
{
    int idx = blockIdx.x * blockDim.x + threadIdx.x;   // 0 .. 262143
    int o = idx >> 9;
    int i = idx & 511;
    const float* Ws = (o < 256) ? Wax1 : Warg1;
    int ro = o & 255;
    float w;
    if (i < 256) {
        w = Ws[ro * 512 + i] + Ws[ro * 512 + 256 + i];
    } else {
        int ii = i - 256;
        w = 0.5f * (Ws[ro * 512 + 256 + ii] - Ws[ro * 512 + ii]);
    }
    g_w1c[o * 512 + i] = w;
    if (i == 0)
        g_b1c[o] = (o < 256) ? bax1[o] : barg1[o - 256];
}

// ---------------------------------------------------------------------------
// TF32 GEMM, register-split + cp.async 3-stage pipeline, CTA 128x128.
// full=1: 3xTF32 (acc += Ah*Bl + Al*Bh + Ah*Bh), error ~2^-22.
// full=0: plain 1-pass tf32 (acc += Ah*Bh), error ~2^-11 — used only for the
//         arg/gate branch where sigmoid damping makes it harmless.
// 8 warps (2x4), warp tile 64x32, mma.m16n8k8.
// ---------------------------------------------------------------------------
__device__ __forceinline__ unsigned f2tf(float f)
{
    unsigned u;
    asm("cvt.rna.tf32.f32 %0, %1;" : "=r"(u) : "f"(f));
    return u;
}

__device__ __forceinline__ void split2(float v, unsigned& h, unsigned& l)
{
    h = f2tf(v);
    l = __float_as_uint(v - __uint_as_float(h));
}

#define MMA(d, a0, a1, a2, a3, b0, b1)                                        \
    asm volatile(                                                             \
        "mma.sync.aligned.m16n8k8.row.col.f32.tf32.tf32.f32 "                 \
        "{%0,%1,%2,%3}, {%4,%5,%6,%7}, {%8,%9}, {%0,%1,%2,%3};"               \
        : "+f"(d[0]), "+f"(d[1]), "+f"(d[2]), "+f"(d[3])                      \
        : "r"(a0), "r"(a1), "r"(a2), "r"(a3), "r"(b0), "r"(b1))

__global__ __launch_bounds__(NTH, 2)
void gemm_tf32(const float* __restrict__ src0, int lda0,
               const float* __restrict__ src1, int lda1, int K0, int K,
               const float* __restrict__ W, int ldw,
               const float* __restrict__ bias,
               float* __restrict__ C, int ldc, int relu, int full)
{
    extern __shared__ float sm[];

    const int tid  = threadIdx.x;
    const int lane = tid & 31;
    const int wid  = tid >> 5;
    const int gp   = lane >> 2;      // 0..7
    const int tq   = lane & 3;       // 0..3
    const int wm   = wid >> 2;       // 0..1  (64-row half)
    const int wn   = wid & 3;        // 0..3  (32-col slice)
    const int mbase = blockIdx.y * TM;
    const int nbase = blockIdx.x * TN;
    const int NCH = K / KC;

    // ---- cp.async stage of chunk ch into ring slot ch%3 ----
    auto issue = [&](int ch) {
        int kg = ch * KC;
        const float* S;
        int ld, kk;
        if (kg < K0) { S = src0; ld = lda0; kk = kg; }
        else         { S = src1; ld = lda1; kk = kg - K0; }
        float* As_ = sm + (ch % STG) * STAGEW;
        float* Bs_ = As_ + ABUF;
        #pragma unroll
        for (int i = 0; i < 2; i++) {
            int idx = tid + i * 256;     // 0..511 float4s
            int row = idx >> 2;          // 0..127
            int c4  = idx & 3;           // 0..3
            const float* gA = S + (size_t)(mbase + row) * ld + kk + c4 * 4;
            const float* gB = W + (size_t)(nbase + row) * ldw + kg + c4 * 4;
            unsigned dA = (unsigned)__cvta_generic_to_shared(&As_[row * KSW + c4 * 4]);
            unsigned dB = (unsigned)__cvta_generic_to_shared(&Bs_[row * KSW + c4 * 4]);
            asm volatile("cp.async.cg.shared.global [%0], [%1], 16;" :: "r"(dA), "l"(gA));
            asm volatile("cp.async.cg.shared.global [%0], [%1], 16;" :: "r"(dB), "l"(gB));
        }
        asm volatile("cp.async.commit_group;" ::: "memory");
    };

    float acc[4][4][4];
    #pragma unroll
    for (int a = 0; a < 4; a++)
        #pragma unroll
        for (int b = 0; b < 4; b++)
            #pragma unroll
            for (int c = 0; c < 4; c++) acc[a][b][c] = 0.f;

    issue(0);
    if (NCH > 1) issue(1);

    for (int ch = 0; ch < NCH; ++ch) {
        // wait for chunk ch (leave ch+1 in flight if it exists)
        if (ch + 1 < NCH)
            asm volatile("cp.async.wait_group 1;" ::: "memory");
        else
            asm volatile("cp.async.wait_group 0;" ::: "memory");
        __syncthreads();

        // prefetch chunk ch+2 into slot (ch+2)%3 == (ch-1)%3, freed by the
        // sync above (all warps finished compute(ch-1) before this barrier).
        if (ch + 2 < NCH) issue(ch + 2);

        // ---- compute chunk ch from ring slot ----
        const float* As_ = sm + (ch % STG) * STAGEW;
        const float* Bs_ = As_ + ABUF;
        #pragma unroll
        for (int ks = 0; ks < 2; ks++) {
            int kk = ks * 8;
            unsigned ah[4][4], al[4][4], bh[4][2], bl[4][2];
            #pragma unroll
            for (int mt = 0; mt < 4; mt++) {
                int r0 = wm * 64 + mt * 16 + gp;
                float v0 = As_[r0 * KSW + kk + tq];
                float v1 = As_[(r0 + 8) * KSW + kk + tq];
                float v2 = As_[r0 * KSW + kk + tq + 4];
                float v3 = As_[(r0 + 8) * KSW + kk + tq + 4];
                if (full) {
                    split2(v0, ah[mt][0], al[mt][0]);
                    split2(v1, ah[mt][1], al[mt][1]);
                    split2(v2, ah[mt][2], al[mt][2]);
                    split2(v3, ah[mt][3], al[mt][3]);
                } else {
                    ah[mt][0] = f2tf(v0); ah[mt][1] = f2tf(v1);
                    ah[mt][2] = f2tf(v2); ah[mt][3] = f2tf(v3);
                }
            }
            #pragma unroll
            for (int nt = 0; nt < 4; nt++) {
                int n0 = wn * 32 + nt * 8 + gp;
                float v0 = Bs_[n0 * KSW + kk + tq];
                float v1 = Bs_[n0 * KSW + kk + tq + 4];
                if (full) {
                    split2(v0, bh[nt][0], bl[nt][0]);
                    split2(v1, bh[nt][1], bl[nt][1]);
                } else {
                    bh[nt][0] = f2tf(v0); bh[nt][1] = f2tf(v1);
                }
            }
            #pragma unroll
            for (int mt = 0; mt < 4; mt++)
                #pragma unroll
                for (int nt = 0; nt < 4; nt++) {
                    if (full) {
                        MMA(acc[mt][nt], ah[mt][0], ah[mt][1], ah[mt][2], ah[mt][3],
                            bl[nt][0], bl[nt][1]);
                        MMA(acc[mt][nt], al[mt][0], al[mt][1], al[mt][2], al[mt][3],
                            bh[nt][0], bh[nt][1]);
                    }
                    MMA(acc[mt][nt], ah[mt][0], ah[mt][1], ah[mt][2], ah[mt][3],
                        bh[nt][0], bh[nt][1]);
                }
        }
    }

    // ---- epilogue: bias (+relu), store ----
    #pragma unroll
    for (int mt = 0; mt < 4; mt++) {
        int r0 = mbase + wm * 64 + mt * 16 + gp;
        #pragma unroll
        for (int nt = 0; nt < 4; nt++) {
            int c0 = nbase + wn * 32 + nt * 8 + tq * 2;
            float bv0 = bias[c0];
            float bv1 = bias[c0 + 1];
            float v;
            v = acc[mt][nt][0] + bv0; if (relu) v = fmaxf(v, 0.f);
            C[(size_t)r0 * ldc + c0] = v;
            v = acc[mt][nt][1] + bv1; if (relu) v = fmaxf(v, 0.f);
            C[(size_t)r0 * ldc + c0 + 1] = v;
            v = acc[mt][nt][2] + bv0; if (relu) v = fmaxf(v, 0.f);
            C[(size_t)(r0 + 8) * ldc + c0] = v;
            v = acc[mt][nt][3] + bv1; if (relu) v = fmaxf(v, 0.f);
            C[(size_t)(r0 + 8) * ldc + c0 + 1] = v;
        }
    }
}

// ---------------------------------------------------------------------------
// Mean over N of the arg half of h1:  hb[bh][c] = mean_n h1[n*BH+bh][256+c]
// ---------------------------------------------------------------------------
__global__ void meanpool_kernel(const float* __restrict__ h1, float* __restrict__ hb)
{
    int i = blockIdx.x * blockDim.x + threadIdx.x;   // 0 .. 32768*64-1 (float4s)
    int bh = i >> 6;
    int c4 = i & 63;
    float4 s = make_float4(0.f, 0.f, 0.f, 0.f);
    #pragma unroll
    for (int n = 0; n < 4; n++) {
        const float* p = h1 + (size_t)(n * BH + bh) * 512 + 256 + c4 * 4;
        float4 v = *(const float4*)p;
        s.x += v.x; s.y += v.y; s.z += v.z; s.w += v.w;
    }
    float4 o = make_float4(s.x * 0.25f, s.y * 0.25f, s.z * 0.25f, s.w * 0.25f);
    *(float4*)(hb + (size_t)bh * 256 + c4 * 4) = o;
}

// ---------------------------------------------------------------------------
// Epilogue: per (bh, d): softmax over N=4 of s, circular mean via atan
// correction; gate = sigmoid(t); arg_out = min_n(arg) * gate.
// ---------------------------------------------------------------------------
__global__ void epilogue_kernel(const float* __restrict__ axisE,
                                const float* __restrict__ argE,
                                float* __restrict__ out)
{
    int idx = blockIdx.x * blockDim.x + threadIdx.x;   // 0 .. BHD-1
    int bh = idx >> 8;
    int d  = idx & 255;

    float s[4], axv[4], agv[4];
    #pragma unroll
    for (int n = 0; n < 4; n++) {
        size_t r = (size_t)n * BH + bh;
        s[n]   = g_s[r * 256 + d];
        axv[n] = axisE[r * 256 + d];
        agv[n] = argE [r * 256 + d];
    }
    float t = g_t[(size_t)bh * 256 + d];

    float m = fmaxf(fmaxf(s[0], s[1]), fmaxf(s[2], s[3]));
    float e[4], se = 0.f;
    #pragma unroll
    for (int n = 0; n < 4; n++) { e[n] = expf(s[n] - m); se += e[n]; }
    float inv = 1.f / se;

    float x = 0.f, y = 0.f;
    #pragma unroll
    for (int n = 0; n < 4; n++) {
        float sn, cn;
        sincosf(axv[n], &sn, &cn);
        float w = e[n] * inv;
        x += w * cn;
        y += w * sn;
    }
    if (fabsf(x) < 0.001f) x = 0.001f;   // jnp.where(|x|<1e-3, +1e-3, x)
    float ao = atanf(y / x);
    if (x < 0.f) ao += (y < 0.f) ? -3.14159265358979f : 3.14159265358979f;

    float gate = 1.f / (1.f + expf(-t));
    float mn = fminf(fminf(agv[0], agv[1]), fminf(agv[2], agv[3]));

    out[idx]       = ao;
    out[BHD + idx] = mn * gate;
}

// ---------------------------------------------------------------------------
extern "C" void kernel_launch(void* const* d_in, const int* in_sizes, int n_in,
                              void* d_out, int out_size)
{
    const float* axisE = (const float*)d_in[0];
    const float* argE  = (const float*)d_in[1];
    const float* Wax1  = (const float*)d_in[2];
    const float* bax1  = (const float*)d_in[3];
    const float* Warg1 = (const float*)d_in[4];
    const float* barg1 = (const float*)d_in[5];
    const float* Wax2  = (const float*)d_in[6];
    const float* bax2  = (const float*)d_in[7];
    const float* Warg2 = (const float*)d_in[8];
    const float* barg2 = (const float*)d_in[9];

    float *h1, *sS, *hb, *tT, *w1c, *b1c;
    cudaGetSymbolAddress((void**)&h1,  g_h1);
    cudaGetSymbolAddress((void**)&sS,  g_s);
    cudaGetSymbolAddress((void**)&hb,  g_hb);
    cudaGetSymbolAddress((void**)&tT,  g_t);
    cudaGetSymbolAddress((void**)&w1c, g_w1c);
    cudaGetSymbolAddress((void**)&b1c, g_b1c);

    cudaFuncSetAttribute(gemm_tf32, cudaFuncAttributeMaxDynamicSharedMemorySize,
                         SMB);

    // Fold layer-1 weights
    prep_kernel<<<1024, 256>>>(Wax1, bax1, Warg1, barg1);

    // GEMM1a (axis half, 3xTF32): h1[:,0:256] = relu([axis,arg] @ W1c[0:256]^T + b)
    gemm_tf32<<<dim3(2, R_TOTAL / TM), NTH, SMB>>>(
        axisE, 256, argE, 256, 256, 512, w1c, 512, b1c, h1, 512, 1, 1);

    // GEMM2a (3xTF32): s = h1[:,0:256] @ W_axis2^T + b_axis2   [131072 x 256]
    gemm_tf32<<<dim3(2, R_TOTAL / TM), NTH, SMB>>>(
        h1, 512, h1, 512, 256, 256, Wax2, 256, bax2, sS, 256, 0, 1);

    // GEMM1b (arg half, 1-pass tf32 — sigmoid-damped branch tolerates 2^-11):
    // h1[:,256:512] = relu([axis,arg] @ W1c[256:512]^T + b)
    gemm_tf32<<<dim3(2, R_TOTAL / TM), NTH, SMB>>>(
        axisE, 256, argE, 256, 256, 512, w1c + 256 * 512, 512, b1c + 256,
        h1 + 256, 512, 1, 0);

    // Mean over N of arg-branch h1 -> hb [32768 x 256]
    meanpool_kernel<<<BH * 64 / 256, 256>>>(h1, hb);

    // GEMM2b (3xTF32): t = hb @ W_arg2^T + b_arg2   [32768 x 256]
    gemm_tf32<<<dim3(2, BH / TM), NTH, SMB>>>(
        hb, 256, hb, 256, 256, 256, Warg2, 256, barg2, tT, 256, 0, 1);

    // Fused softmax / circular mean / gate epilogue
    epilogue_kernel<<<BHD / 256, 256>>>(axisE, argE, (float*)d_out);
}

// round 17
// speedup vs baseline: 1.2233x; 1.2233x over previous
#include <cuda_runtime.h>
#include <cstdint>

// Problem constants
#define R_TOTAL 131072      // N*B*H rows
#define BH      32768       // B*H
#define BHD     8388608     // B*DIM
#define TM 128
#define TN 128
#define KC 16               // K-chunk
#define KSW 20              // padded smem row stride (words)
#define NTH 256
#define STG 3               // pipeline stages

#define ABUF   (128 * KSW)          // words per A (or B) stage = 2560
#define STAGEW (2 * ABUF)           // A+B per stage
#define SMB    (STG * STAGEW * 4)   // 61440 bytes

// Scratch (device globals — no allocation allowed in kernel_launch)
__device__ float g_h1[131072 * 512];   // relu(layer1): cols 0-255 axis, 256-511 arg
__device__ float g_s [131072 * 256];   // axis logits
__device__ float g_hb[32768 * 256];    // mean over N of arg-branch h1
__device__ float g_t [32768 * 256];    // gate pre-activation
__device__ float g_w1c[512 * 512];     // folded layer-1 weights
__device__ float g_b1c[512];

// ---------------------------------------------------------------------------
// Prep: fold concat([axis-arg/2, axis+arg/2]) @ W1^T into direct weights on
// [axis, arg]:  coeff(axis) = Wlo + Whi ; coeff(arg) = (Whi - Wlo)/2
// ---------------------------------------------------------------------------
__global__ void prep_kernel(const float* __restrict__ Wax1, const float* __restrict__ bax1,
                            const float* __restrict__ Warg1, const float* __restrict__ barg1)
{
    int idx = blockIdx.x * blockDim.x + threadIdx.x;   // 0 .. 262143
    int o = idx >> 9;
    int i = idx & 511;
    const float* Ws = (o < 256) ? Wax1 : Warg1;
    int ro = o & 255;
    float w;
    if (i < 256) {
        w = Ws[ro * 512 + i] + Ws[ro * 512 + 256 + i];
    } else {
        int ii = i - 256;
        w = 0.5f * (Ws[ro * 512 + 256 + ii] - Ws[ro * 512 + ii]);
    }
    g_w1c[o * 512 + i] = w;
    if (i == 0)
        g_b1c[o] = (o < 256) ? bax1[o] : barg1[o - 256];
}

// ---------------------------------------------------------------------------
// TF32 GEMM body, compile-time FULL, cp.async 3-stage pipeline, CTA 128x128.
// FULL=1: 3xTF32 (acc += Ah*Bl + Al*Bh + Ah*Bh), error ~2^-22.
// FULL=0: plain 1-pass tf32 (acc += Ah*Bh), error ~2^-11 — only for the
//         arg/gate branch where sigmoid damping makes it harmless.
// 8 warps (2x4), warp tile 64x32, mma.m16n8k8.
// ---------------------------------------------------------------------------
__device__ __forceinline__ unsigned f2tf(float f)
{
    unsigned u;
    asm("cvt.rna.tf32.f32 %0, %1;" : "=r"(u) : "f"(f));
    return u;
}

__device__ __forceinline__ void split2(float v, unsigned& h, unsigned& l)
{
    h = f2tf(v);
    l = __float_as_uint(v - __uint_as_float(h));
}

#define MMA(d, a0, a1, a2, a3, b0, b1)                                        \
    asm volatile(                                                             \
        "mma.sync.aligned.m16n8k8.row.col.f32.tf32.tf32.f32 "                 \
        "{%0,%1,%2,%3}, {%4,%5,%6,%7}, {%8,%9}, {%0,%1,%2,%3};"               \
        : "+f"(d[0]), "+f"(d[1]), "+f"(d[2]), "+f"(d[3])                      \
        : "r"(a0), "r"(a1), "r"(a2), "r"(a3), "r"(b0), "r"(b1))

template<int FULL>
__device__ __forceinline__ void gemm_body(
    float* sm,
    const float* __restrict__ src0, int lda0,
    const float* __restrict__ src1, int lda1, int K0, int K,
    const float* __restrict__ W, int ldw,
    const float* __restrict__ bias,
    float* __restrict__ C, int ldc, int relu)
{
    const int tid  = threadIdx.x;
    const int lane = tid & 31;
    const int wid  = tid >> 5;
    const int gp   = lane >> 2;      // 0..7
    const int tq   = lane & 3;       // 0..3
    const int wm   = wid >> 2;       // 0..1  (64-row half)
    const int wn   = wid & 3;        // 0..3  (32-col slice)
    const int mbase = blockIdx.y * TM;
    const int nbase = blockIdx.x * TN;
    const int NCH = K / KC;

    // ---- cp.async stage of chunk ch into ring slot ch%3 ----
    auto issue = [&](int ch) {
        int kg = ch * KC;
        const float* S;
        int ld, kk;
        if (kg < K0) { S = src0; ld = lda0; kk = kg; }
        else         { S = src1; ld = lda1; kk = kg - K0; }
        float* As_ = sm + (ch % STG) * STAGEW;
        float* Bs_ = As_ + ABUF;
        #pragma unroll
        for (int i = 0; i < 2; i++) {
            int idx = tid + i * 256;     // 0..511 float4s
            int row = idx >> 2;          // 0..127
            int c4  = idx & 3;           // 0..3
            const float* gA = S + (size_t)(mbase + row) * ld + kk + c4 * 4;
            const float* gB = W + (size_t)(nbase + row) * ldw + kg + c4 * 4;
            unsigned dA = (unsigned)__cvta_generic_to_shared(&As_[row * KSW + c4 * 4]);
            unsigned dB = (unsigned)__cvta_generic_to_shared(&Bs_[row * KSW + c4 * 4]);
            asm volatile("cp.async.cg.shared.global [%0], [%1], 16;" :: "r"(dA), "l"(gA));
            asm volatile("cp.async.cg.shared.global [%0], [%1], 16;" :: "r"(dB), "l"(gB));
        }
        asm volatile("cp.async.commit_group;" ::: "memory");
    };

    float acc[4][4][4];
    #pragma unroll
    for (int a = 0; a < 4; a++)
        #pragma unroll
        for (int b = 0; b < 4; b++)
            #pragma unroll
            for (int c = 0; c < 4; c++) acc[a][b][c] = 0.f;

    issue(0);
    if (NCH > 1) issue(1);

    for (int ch = 0; ch < NCH; ++ch) {
        // wait for chunk ch (leave ch+1 in flight if it exists)
        if (ch + 1 < NCH)
            asm volatile("cp.async.wait_group 1;" ::: "memory");
        else
            asm volatile("cp.async.wait_group 0;" ::: "memory");
        __syncthreads();

        // prefetch chunk ch+2 into slot (ch+2)%3 == (ch-1)%3, freed by the
        // sync above (all warps finished compute(ch-1) before this barrier).
        if (ch + 2 < NCH) issue(ch + 2);

        // ---- compute chunk ch from ring slot ----
        const float* As_ = sm + (ch % STG) * STAGEW;
        const float* Bs_ = As_ + ABUF;
        #pragma unroll
        for (int ks = 0; ks < 2; ks++) {
            int kk = ks * 8;
            unsigned ah[4][4], al[4][4], bh[4][2], bl[4][2];
            #pragma unroll
            for (int mt = 0; mt < 4; mt++) {
                int r0 = wm * 64 + mt * 16 + gp;
                float v0 = As_[r0 * KSW + kk + tq];
                float v1 = As_[(r0 + 8) * KSW + kk + tq];
                float v2 = As_[r0 * KSW + kk + tq + 4];
                float v3 = As_[(r0 + 8) * KSW + kk + tq + 4];
                if (FULL) {
                    split2(v0, ah[mt][0], al[mt][0]);
                    split2(v1, ah[mt][1], al[mt][1]);
                    split2(v2, ah[mt][2], al[mt][2]);
                    split2(v3, ah[mt][3], al[mt][3]);
                } else {
                    ah[mt][0] = f2tf(v0); ah[mt][1] = f2tf(v1);
                    ah[mt][2] = f2tf(v2); ah[mt][3] = f2tf(v3);
                }
            }
            #pragma unroll
            for (int nt = 0; nt < 4; nt++) {
                int n0 = wn * 32 + nt * 8 + gp;
                float v0 = Bs_[n0 * KSW + kk + tq];
                float v1 = Bs_[n0 * KSW + kk + tq + 4];
                if (FULL) {
                    split2(v0, bh[nt][0], bl[nt][0]);
                    split2(v1, bh[nt][1], bl[nt][1]);
                } else {
                    bh[nt][0] = f2tf(v0); bh[nt][1] = f2tf(v1);
                }
            }
            #pragma unroll
            for (int mt = 0; mt < 4; mt++)
                #pragma unroll
                for (int nt = 0; nt < 4; nt++) {
                    if (FULL) {
                        MMA(acc[mt][nt], ah[mt][0], ah[mt][1], ah[mt][2], ah[mt][3],
                            bl[nt][0], bl[nt][1]);
                        MMA(acc[mt][nt], al[mt][0], al[mt][1], al[mt][2], al[mt][3],
                            bh[nt][0], bh[nt][1]);
                    }
                    MMA(acc[mt][nt], ah[mt][0], ah[mt][1], ah[mt][2], ah[mt][3],
                        bh[nt][0], bh[nt][1]);
                }
        }
    }

    // ---- epilogue: bias (+relu), store ----
    #pragma unroll
    for (int mt = 0; mt < 4; mt++) {
        int r0 = mbase + wm * 64 + mt * 16 + gp;
        #pragma unroll
        for (int nt = 0; nt < 4; nt++) {
            int c0 = nbase + wn * 32 + nt * 8 + tq * 2;
            float bv0 = bias[c0];
            float bv1 = bias[c0 + 1];
            float v;
            v = acc[mt][nt][0] + bv0; if (relu) v = fmaxf(v, 0.f);
            C[(size_t)r0 * ldc + c0] = v;
            v = acc[mt][nt][1] + bv1; if (relu) v = fmaxf(v, 0.f);
            C[(size_t)r0 * ldc + c0 + 1] = v;
            v = acc[mt][nt][2] + bv0; if (relu) v = fmaxf(v, 0.f);
            C[(size_t)(r0 + 8) * ldc + c0] = v;
            v = acc[mt][nt][3] + bv1; if (relu) v = fmaxf(v, 0.f);
            C[(size_t)(r0 + 8) * ldc + c0 + 1] = v;
        }
    }
}

// nfull: CTAs with blockIdx.x < nfull run 3xTF32, the rest run 1-pass tf32.
// The branch is per-CTA uniform and OUTSIDE the mainloop; both bodies are
// compile-time specialized (no branches inside the unrolled MMA loop).
__global__ __launch_bounds__(NTH, 2)
void gemm_tf32(const float* __restrict__ src0, int lda0,
               const float* __restrict__ src1, int lda1, int K0, int K,
               const float* __restrict__ W, int ldw,
               const float* __restrict__ bias,
               float* __restrict__ C, int ldc, int relu, int nfull)
{
    extern __shared__ float sm[];
    if ((int)blockIdx.x < nfull)
        gemm_body<1>(sm, src0, lda0, src1, lda1, K0, K, W, ldw, bias, C, ldc, relu);
    else
        gemm_body<0>(sm, src0, lda0, src1, lda1, K0, K, W, ldw, bias, C, ldc, relu);
}

// ---------------------------------------------------------------------------
// Mean over N of the arg half of h1:  hb[bh][c] = mean_n h1[n*BH+bh][256+c]
// ---------------------------------------------------------------------------
__global__ void meanpool_kernel(const float* __restrict__ h1, float* __restrict__ hb)
{
    int i = blockIdx.x * blockDim.x + threadIdx.x;   // 0 .. 32768*64-1 (float4s)
    int bh = i >> 6;
    int c4 = i & 63;
    float4 s = make_float4(0.f, 0.f, 0.f, 0.f);
    #pragma unroll
    for (int n = 0; n < 4; n++) {
        const float* p = h1 + (size_t)(n * BH + bh) * 512 + 256 + c4 * 4;
        float4 v = *(const float4*)p;
        s.x += v.x; s.y += v.y; s.z += v.z; s.w += v.w;
    }
    float4 o = make_float4(s.x * 0.25f, s.y * 0.25f, s.z * 0.25f, s.w * 0.25f);
    *(float4*)(hb + (size_t)bh * 256 + c4 * 4) = o;
}

// ---------------------------------------------------------------------------
// Epilogue: per (bh, d): softmax over N=4 of s, circular mean via atan
// correction; gate = sigmoid(t); arg_out = min_n(arg) * gate.
// ---------------------------------------------------------------------------
__global__ void epilogue_kernel(const float* __restrict__ axisE,
                                const float* __restrict__ argE,
                                float* __restrict__ out)
{
    int idx = blockIdx.x * blockDim.x + threadIdx.x;   // 0 .. BHD-1
    int bh = idx >> 8;
    int d  = idx & 255;

    float s[4], axv[4], agv[4];
    #pragma unroll
    for (int n = 0; n < 4; n++) {
        size_t r = (size_t)n * BH + bh;
        s[n]   = g_s[r * 256 + d];
        axv[n] = axisE[r * 256 + d];
        agv[n] = argE [r * 256 + d];
    }
    float t = g_t[(size_t)bh * 256 + d];

    float m = fmaxf(fmaxf(s[0], s[1]), fmaxf(s[2], s[3]));
    float e[4], se = 0.f;
    #pragma unroll
    for (int n = 0; n < 4; n++) { e[n] = expf(s[n] - m); se += e[n]; }
    float inv = 1.f / se;

    float x = 0.f, y = 0.f;
    #pragma unroll
    for (int n = 0; n < 4; n++) {
        float sn, cn;
        sincosf(axv[n], &sn, &cn);
        float w = e[n] * inv;
        x += w * cn;
        y += w * sn;
    }
    if (fabsf(x) < 0.001f) x = 0.001f;   // jnp.where(|x|<1e-3, +1e-3, x)
    float ao = atanf(y / x);
    if (x < 0.f) ao += (y < 0.f) ? -3.14159265358979f : 3.14159265358979f;

    float gate = 1.f / (1.f + expf(-t));
    float mn = fminf(fminf(agv[0], agv[1]), fminf(agv[2], agv[3]));

    out[idx]       = ao;
    out[BHD + idx] = mn * gate;
}

// ---------------------------------------------------------------------------
extern "C" void kernel_launch(void* const* d_in, const int* in_sizes, int n_in,
                              void* d_out, int out_size)
{
    const float* axisE = (const float*)d_in[0];
    const float* argE  = (const float*)d_in[1];
    const float* Wax1  = (const float*)d_in[2];
    const float* bax1  = (const float*)d_in[3];
    const float* Warg1 = (const float*)d_in[4];
    const float* barg1 = (const float*)d_in[5];
    const float* Wax2  = (const float*)d_in[6];
    const float* bax2  = (const float*)d_in[7];
    const float* Warg2 = (const float*)d_in[8];
    const float* barg2 = (const float*)d_in[9];

    float *h1, *sS, *hb, *tT, *w1c, *b1c;
    cudaGetSymbolAddress((void**)&h1,  g_h1);
    cudaGetSymbolAddress((void**)&sS,  g_s);
    cudaGetSymbolAddress((void**)&hb,  g_hb);
    cudaGetSymbolAddress((void**)&tT,  g_t);
    cudaGetSymbolAddress((void**)&w1c, g_w1c);
    cudaGetSymbolAddress((void**)&b1c, g_b1c);

    cudaFuncSetAttribute(gemm_tf32, cudaFuncAttributeMaxDynamicSharedMemorySize,
                         SMB);

    // Fold layer-1 weights
    prep_kernel<<<1024, 256>>>(Wax1, bax1, Warg1, barg1);

    // GEMM1 (mixed): h1 = relu([axis,arg] @ W1c^T + b1c), [131072 x 512].
    // N-blocks 0-1 (axis half) run 3xTF32; N-blocks 2-3 (arg half) run 1-pass.
    gemm_tf32<<<dim3(4, R_TOTAL / TM), NTH, SMB>>>(
        axisE, 256, argE, 256, 256, 512, w1c, 512, b1c, h1, 512, 1, 2);

    // GEMM2a (3xTF32): s = h1[:,0:256] @ W_axis2^T + b_axis2   [131072 x 256]
    gemm_tf32<<<dim3(2, R_TOTAL / TM), NTH, SMB>>>(
        h1, 512, h1, 512, 256, 256, Wax2, 256, bax2, sS, 256, 0, 2);

    // Mean over N of arg-branch h1 -> hb [32768 x 256]
    meanpool_kernel<<<BH * 64 / 256, 256>>>(h1, hb);

    // GEMM2b (3xTF32): t = hb @ W_arg2^T + b_arg2   [32768 x 256]
    gemm_tf32<<<dim3(2, BH / TM), NTH, SMB>>>(
        hb, 256, hb, 256, 256, 256, Warg2, 256, barg2, tT, 256, 0, 2);

    // Fused softmax / circular mean / gate epilogue
    epilogue_kernel<<<BHD / 256, 256>>>(axisE, argE, (float*)d_out);
}